// round 1
// baseline (speedup 1.0000x reference)
#include <cuda_runtime.h>
#include <cuda_bf16.h>
#include <cfloat>
#include <cstdint>
#include <cstddef>

// Problem constants (fixed by the dataset)
#define BATCH 16
#define SEQ   2048
#define DIM   64
#define KTOP  128

// 268 MB scratch for the similarity matrix sim[b][q][k] (q = v1 pos, k = v2 pos)
__device__ float g_sim[(size_t)BATCH * SEQ * SEQ];

// ---------------------------------------------------------------------------
// Order-preserving float -> uint key (larger float => larger key)
// ---------------------------------------------------------------------------
__device__ __forceinline__ unsigned f2key(float f) {
    unsigned u = __float_as_uint(f);
    return u ^ (((unsigned)((int)u >> 31)) | 0x80000000u);
}

// ---------------------------------------------------------------------------
// Block reductions (256 threads)
// ---------------------------------------------------------------------------
__device__ __forceinline__ float block_max(float v, float* red) {
#pragma unroll
    for (int o = 16; o > 0; o >>= 1) v = fmaxf(v, __shfl_xor_sync(0xffffffffu, v, o));
    __syncthreads();
    if ((threadIdx.x & 31) == 0) red[threadIdx.x >> 5] = v;
    __syncthreads();
    return fmaxf(fmaxf(fmaxf(red[0], red[1]), fmaxf(red[2], red[3])),
                 fmaxf(fmaxf(red[4], red[5]), fmaxf(red[6], red[7])));
}

__device__ __forceinline__ float block_sum(float v, float* red) {
#pragma unroll
    for (int o = 16; o > 0; o >>= 1) v += __shfl_xor_sync(0xffffffffu, v, o);
    __syncthreads();
    if ((threadIdx.x & 31) == 0) red[threadIdx.x >> 5] = v;
    __syncthreads();
    return ((red[0] + red[1]) + (red[2] + red[3])) + ((red[4] + red[5]) + (red[6] + red[7]));
}

// ---------------------------------------------------------------------------
// GEMM: sim[b][q][k] = sum_d v1[b][q][d] * v2[b][k][d]
// 128x128 tile per block, 256 threads, 8x8 per thread, K = 64 (full depth)
// ---------------------------------------------------------------------------
__global__ __launch_bounds__(256, 2) void gemm_kernel(const float* __restrict__ v1,
                                                      const float* __restrict__ v2) {
    extern __shared__ float dsm[];
    float (*AsT)[128] = (float (*)[128])dsm;              // [d][q_local]
    float (*BsT)[128] = (float (*)[128])(dsm + 64 * 128); // [d][k_local]

    const int t  = threadIdx.x;
    const int b  = blockIdx.z;
    const int q0 = blockIdx.y * 128;
    const int k0 = blockIdx.x * 128;

    // cooperative transposed tile loads
    {
        const int r  = t & 127;
        const int ds = (t >> 7) * 32;
        const float* a  = v1 + ((size_t)b * SEQ + q0 + r) * DIM + ds;
        const float* bp = v2 + ((size_t)b * SEQ + k0 + r) * DIM + ds;
#pragma unroll
        for (int i = 0; i < 8; i++) {
            float4 va = *(const float4*)(a + 4 * i);
            AsT[ds + 4 * i + 0][r] = va.x;
            AsT[ds + 4 * i + 1][r] = va.y;
            AsT[ds + 4 * i + 2][r] = va.z;
            AsT[ds + 4 * i + 3][r] = va.w;
            float4 vb = *(const float4*)(bp + 4 * i);
            BsT[ds + 4 * i + 0][r] = vb.x;
            BsT[ds + 4 * i + 1][r] = vb.y;
            BsT[ds + 4 * i + 2][r] = vb.z;
            BsT[ds + 4 * i + 3][r] = vb.w;
        }
    }
    __syncthreads();

    const int tx = t & 15;
    const int ty = t >> 4;

    float acc[8][8];
#pragma unroll
    for (int i = 0; i < 8; i++)
#pragma unroll
        for (int j = 0; j < 8; j++) acc[i][j] = 0.f;

#pragma unroll 8
    for (int d = 0; d < 64; d++) {
        float ar[8], br[8];
        *(float4*)&ar[0] = *(const float4*)&AsT[d][ty * 8];
        *(float4*)&ar[4] = *(const float4*)&AsT[d][ty * 8 + 4];
        *(float4*)&br[0] = *(const float4*)&BsT[d][tx * 8];
        *(float4*)&br[4] = *(const float4*)&BsT[d][tx * 8 + 4];
#pragma unroll
        for (int i = 0; i < 8; i++)
#pragma unroll
            for (int j = 0; j < 8; j++) acc[i][j] = fmaf(ar[i], br[j], acc[i][j]);
    }

    float* orow = g_sim + ((size_t)b * SEQ + q0 + ty * 8) * SEQ + k0 + tx * 8;
#pragma unroll
    for (int i = 0; i < 8; i++) {
        *(float4*)(orow + (size_t)i * SEQ)     = make_float4(acc[i][0], acc[i][1], acc[i][2], acc[i][3]);
        *(float4*)(orow + (size_t)i * SEQ + 4) = make_float4(acc[i][4], acc[i][5], acc[i][6], acc[i][7]);
    }
}

// ---------------------------------------------------------------------------
// Per-row top-k softmax reduce core.
// Scores live in shared memory (element i at sc[i*stride]), already masked
// (-FLT_MAX at padded key positions). Computes:
//   m = max, denom = sum exp(s-m) over all 2048,
//   T = key of 128th-largest score (exact, 4-pass radix select),
//   out[d] = sum_{sel} exp(s-m) * V[i][d] / denom   (deterministic order)
// ---------------------------------------------------------------------------
struct TopkSmem {
    unsigned hist[256];
    float    red[8];
    int      sel_idx[KTOP];
    float    sel_w[KTOP];
    int      warpcnt[8];
    int      warpbase[8];
    int      cnt;
    int      bin;
    int      wantn;
    float    racc[256];
};

__device__ void process_topk(const float* sc, int stride,
                             const float* __restrict__ Vb,
                             float* __restrict__ outrow,
                             bool row_masked, TopkSmem* sm) {
    const int t = threadIdx.x;

    // ---- max ----
    float lm = -FLT_MAX;
#pragma unroll
    for (int c = 0; c < 8; c++) lm = fmaxf(lm, sc[(size_t)(c * 256 + t) * stride]);
    const float m = block_max(lm, sm->red);

    // ---- denom + first radix-pass histogram (fused sweep) ----
    sm->hist[t] = 0;
    __syncthreads();
    float ld = 0.f;
#pragma unroll
    for (int c = 0; c < 8; c++) {
        float v = sc[(size_t)(c * 256 + t) * stride];
        ld += __expf(v - m);
        atomicAdd(&sm->hist[f2key(v) >> 24], 1u);
    }
    const float denom = block_sum(ld, sm->red);  // internal barriers order the atomics too
    __syncthreads();

    // ---- radix select: exact key of the 128th largest ----
    unsigned prefix = 0;
    int want = KTOP;
#pragma unroll
    for (int pass = 0; pass < 4; pass++) {
        const int shift = 24 - pass * 8;
        if (pass > 0) {
            sm->hist[t] = 0;
            __syncthreads();
#pragma unroll
            for (int c = 0; c < 8; c++) {
                unsigned u = f2key(sc[(size_t)(c * 256 + t) * stride]);
                if ((u >> (shift + 8)) == (prefix >> (shift + 8)))
                    atomicAdd(&sm->hist[(u >> shift) & 255], 1u);
            }
            __syncthreads();
        }
        // suffix-sum scan over 256 bins (Hillis-Steele)
#pragma unroll
        for (int off = 1; off < 256; off <<= 1) {
            unsigned add = (t + off < 256) ? sm->hist[t + off] : 0u;
            __syncthreads();
            sm->hist[t] += add;
            __syncthreads();
        }
        unsigned cum  = sm->hist[t];
        unsigned cumn = (t < 255) ? sm->hist[t + 1] : 0u;
        if (cum >= (unsigned)want && cumn < (unsigned)want) {
            sm->bin   = t;
            sm->wantn = want - (int)cumn;
        }
        __syncthreads();
        prefix |= ((unsigned)sm->bin) << shift;
        want = sm->wantn;
        __syncthreads();
    }
    const unsigned T = prefix;

    // ---- deterministic (index-ordered) compaction of keys >= T ----
    if (t == 0) sm->cnt = 0;
    __syncthreads();
#pragma unroll
    for (int c = 0; c < 8; c++) {
        const int i = c * 256 + t;
        float v  = sc[(size_t)i * stride];
        bool sel = (f2key(v) >= T);
        unsigned bal = __ballot_sync(0xffffffffu, sel);
        if ((t & 31) == 0) sm->warpcnt[t >> 5] = __popc(bal);
        __syncthreads();
        if (t == 0) {
            int base = sm->cnt;
#pragma unroll
            for (int w = 0; w < 8; w++) { sm->warpbase[w] = base; base += sm->warpcnt[w]; }
            sm->cnt = base;
        }
        __syncthreads();
        if (sel) {
            int pos = sm->warpbase[t >> 5] + __popc(bal & ((1u << (t & 31)) - 1u));
            if (pos < KTOP) {
                sm->sel_idx[pos] = i;
                sm->sel_w[pos]   = __expf(v - m);
            }
        }
        __syncthreads();
    }
    const int n = min(sm->cnt, KTOP);

    // ---- gather-accumulate: 4 partial slots x 64 dims ----
    const int d    = t & 63;
    const int part = t >> 6;
    float acc = 0.f;
#pragma unroll 4
    for (int j = part; j < n; j += 4)
        acc += sm->sel_w[j] * __ldg(&Vb[(size_t)sm->sel_idx[j] * DIM + d]);
    sm->racc[t] = acc;
    __syncthreads();
    if (part == 0) {
        float tot = sm->racc[d] + sm->racc[d + 64] + sm->racc[d + 128] + sm->racc[d + 192];
        outrow[d] = row_masked ? 0.f : tot * (1.f / denom);
    }
    __syncthreads();
}

// ---------------------------------------------------------------------------
// Direction 1: rows of sim. block = (b, q). out1[b][q][:] from v2.
// ---------------------------------------------------------------------------
__global__ __launch_bounds__(256) void topk_row_kernel(const float* __restrict__ V,
                                                       const unsigned char* __restrict__ kmask,
                                                       const unsigned char* __restrict__ rmask,
                                                       float* __restrict__ out) {
    __shared__ float    s[SEQ];
    __shared__ TopkSmem sm;
    const int t = threadIdx.x;
    const int r = blockIdx.x;
    const int b = blockIdx.y;

    const float* srow = g_sim + ((size_t)b * SEQ + r) * SEQ;
    const unsigned char* km = kmask + (size_t)b * SEQ;
#pragma unroll
    for (int c = 0; c < 8; c++) {
        int i = c * 256 + t;
        float v = srow[i];
        if (km[i]) v = -FLT_MAX;
        s[i] = v;
    }
    __syncthreads();

    const bool rmk = rmask[(size_t)b * SEQ + r] != 0;
    process_topk(s, 1, V + (size_t)b * SEQ * DIM,
                 out + ((size_t)b * SEQ + r) * DIM, rmk, &sm);
}

// ---------------------------------------------------------------------------
// Direction 2: columns of sim. block = (b, 8 columns). Loads a padded smem
// transpose tile [2048][9], then runs the same core 8 times with stride 9.
// out2[b][m][:] from v1.
// ---------------------------------------------------------------------------
__global__ __launch_bounds__(256) void topk_col_kernel(const float* __restrict__ V,
                                                       const unsigned char* __restrict__ kmask,
                                                       const unsigned char* __restrict__ rmask,
                                                       float* __restrict__ out) {
    extern __shared__ float s2[];  // [2048][9] (pad for bank-conflict-free strided reads)
    __shared__ TopkSmem sm;
    const int t  = threadIdx.x;
    const int m0 = blockIdx.x * 8;
    const int b  = blockIdx.y;

    const float* sb = g_sim + (size_t)b * SEQ * SEQ;
    const unsigned char* km = kmask + (size_t)b * SEQ;
#pragma unroll 8
    for (int e = t; e < SEQ * 8; e += 256) {
        int q = e >> 3, mi = e & 7;
        float v = __ldg(&sb[(size_t)q * SEQ + m0 + mi]);
        if (km[q]) v = -FLT_MAX;
        s2[q * 9 + mi] = v;
    }
    __syncthreads();

    const float* Vb = V + (size_t)b * SEQ * DIM;
    for (int mi = 0; mi < 8; mi++) {
        const bool rmk = rmask[(size_t)b * SEQ + m0 + mi] != 0;
        process_topk(s2 + mi, 9, Vb,
                     out + ((size_t)b * SEQ + m0 + mi) * DIM, rmk, &sm);
    }
}

// ---------------------------------------------------------------------------
// Launch
// ---------------------------------------------------------------------------
extern "C" void kernel_launch(void* const* d_in, const int* in_sizes, int n_in,
                              void* d_out, int out_size) {
    const float*         v1  = (const float*)d_in[0];
    const unsigned char* v1m = (const unsigned char*)d_in[1];
    const float*         v2  = (const float*)d_in[2];
    const unsigned char* v2m = (const unsigned char*)d_in[3];
    float* out1 = (float*)d_out;
    float* out2 = out1 + (size_t)BATCH * SEQ * DIM;

    const int gemm_smem = 2 * 64 * 128 * (int)sizeof(float);   // 65536
    const int col_smem  = SEQ * 9 * (int)sizeof(float);        // 73728
    cudaFuncSetAttribute((const void*)gemm_kernel,
                         cudaFuncAttributeMaxDynamicSharedMemorySize, gemm_smem);
    cudaFuncSetAttribute((const void*)topk_col_kernel,
                         cudaFuncAttributeMaxDynamicSharedMemorySize, col_smem);

    dim3 gg(SEQ / 128, SEQ / 128, BATCH);
    gemm_kernel<<<gg, 256, gemm_smem>>>(v1, v2);

    dim3 gr(SEQ, BATCH);
    topk_row_kernel<<<gr, 256>>>(v2, v2m, v1m, out1);

    dim3 gc(SEQ / 8, BATCH);
    topk_col_kernel<<<gc, 256, col_smem>>>(v1, v1m, v2m, out2);
}

// round 2
// speedup vs baseline: 1.3328x; 1.3328x over previous
#include <cuda_runtime.h>
#include <cuda_bf16.h>
#include <cfloat>
#include <cstdint>
#include <cstddef>

#define BATCH 16
#define SEQ   2048
#define DIM   64
#define KTOP  128

// 268 MB each: sim[b][q][k] and its transpose simT[b][k][q]
__device__ float g_sim [(size_t)BATCH * SEQ * SEQ];
__device__ float g_simT[(size_t)BATCH * SEQ * SEQ];

// Order-preserving float -> uint key (larger float => larger key)
__device__ __forceinline__ unsigned f2key(float f) {
    unsigned u = __float_as_uint(f);
    return u ^ (((unsigned)((int)u >> 31)) | 0x80000000u);
}

// ---------------------------------------------------------------------------
// GEMM: sim = v1 @ v2^T ; also writes simT from registers.
// 128x128 tile per block, 256 threads, 8x8 per thread, K = 64 full depth.
// ---------------------------------------------------------------------------
__global__ __launch_bounds__(256, 2) void gemm_kernel(const float* __restrict__ v1,
                                                      const float* __restrict__ v2) {
    extern __shared__ float dsm[];
    float (*AsT)[128] = (float (*)[128])dsm;              // [d][q_local]
    float (*BsT)[128] = (float (*)[128])(dsm + 64 * 128); // [d][k_local]

    const int t  = threadIdx.x;
    const int b  = blockIdx.z;
    const int q0 = blockIdx.y * 128;
    const int k0 = blockIdx.x * 128;

    {
        const int r  = t & 127;
        const int ds = (t >> 7) * 32;
        const float* a  = v1 + ((size_t)b * SEQ + q0 + r) * DIM + ds;
        const float* bp = v2 + ((size_t)b * SEQ + k0 + r) * DIM + ds;
#pragma unroll
        for (int i = 0; i < 8; i++) {
            float4 va = *(const float4*)(a + 4 * i);
            AsT[ds + 4 * i + 0][r] = va.x;
            AsT[ds + 4 * i + 1][r] = va.y;
            AsT[ds + 4 * i + 2][r] = va.z;
            AsT[ds + 4 * i + 3][r] = va.w;
            float4 vb = *(const float4*)(bp + 4 * i);
            BsT[ds + 4 * i + 0][r] = vb.x;
            BsT[ds + 4 * i + 1][r] = vb.y;
            BsT[ds + 4 * i + 2][r] = vb.z;
            BsT[ds + 4 * i + 3][r] = vb.w;
        }
    }
    __syncthreads();

    const int tx = t & 15;
    const int ty = t >> 4;

    float acc[8][8];
#pragma unroll
    for (int i = 0; i < 8; i++)
#pragma unroll
        for (int j = 0; j < 8; j++) acc[i][j] = 0.f;

#pragma unroll 8
    for (int d = 0; d < 64; d++) {
        float ar[8], br[8];
        *(float4*)&ar[0] = *(const float4*)&AsT[d][ty * 8];
        *(float4*)&ar[4] = *(const float4*)&AsT[d][ty * 8 + 4];
        *(float4*)&br[0] = *(const float4*)&BsT[d][tx * 8];
        *(float4*)&br[4] = *(const float4*)&BsT[d][tx * 8 + 4];
#pragma unroll
        for (int i = 0; i < 8; i++)
#pragma unroll
            for (int j = 0; j < 8; j++) acc[i][j] = fmaf(ar[i], br[j], acc[i][j]);
    }

    float* orow = g_sim + ((size_t)b * SEQ + q0 + ty * 8) * SEQ + k0 + tx * 8;
#pragma unroll
    for (int i = 0; i < 8; i++) {
        *(float4*)(orow + (size_t)i * SEQ)     = make_float4(acc[i][0], acc[i][1], acc[i][2], acc[i][3]);
        *(float4*)(orow + (size_t)i * SEQ + 4) = make_float4(acc[i][4], acc[i][5], acc[i][6], acc[i][7]);
    }
    float* trow = g_simT + ((size_t)b * SEQ + k0 + tx * 8) * SEQ + q0 + ty * 8;
#pragma unroll
    for (int j = 0; j < 8; j++) {
        *(float4*)(trow + (size_t)j * SEQ)     = make_float4(acc[0][j], acc[1][j], acc[2][j], acc[3][j]);
        *(float4*)(trow + (size_t)j * SEQ + 4) = make_float4(acc[4][j], acc[5][j], acc[6][j], acc[7][j]);
    }
}

// ---------------------------------------------------------------------------
// Block scan helpers (256 threads): shuffle within warp + 8-word fixup.
// ---------------------------------------------------------------------------
__device__ __forceinline__ unsigned suffix_excl_256(unsigned v, unsigned* ws) {
    __syncthreads();  // protect ws reuse across calls
    const int lane = threadIdx.x & 31;
    unsigned s = v;
#pragma unroll
    for (int o = 1; o < 32; o <<= 1) {
        unsigned n = __shfl_down_sync(0xffffffffu, s, o);
        if (lane + o < 32) s += n;
    }
    if (lane == 0) ws[threadIdx.x >> 5] = s;  // warp total
    __syncthreads();
    unsigned cross = 0;
    const int w = threadIdx.x >> 5;
#pragma unroll
    for (int i = 0; i < 8; i++)
        if (i > w) cross += ws[i];
    return cross + (s - v);
}

__device__ __forceinline__ unsigned prefix_excl_256(unsigned v, unsigned* ws) {
    __syncthreads();
    const int lane = threadIdx.x & 31;
    unsigned s = v;
#pragma unroll
    for (int o = 1; o < 32; o <<= 1) {
        unsigned n = __shfl_up_sync(0xffffffffu, s, o);
        if (lane - o >= 0) s += n;
    }
    if (lane == 31) ws[threadIdx.x >> 5] = s;
    __syncthreads();
    unsigned cross = 0;
    const int w = threadIdx.x >> 5;
#pragma unroll
    for (int i = 0; i < 8; i++)
        if (i < w) cross += ws[i];
    return cross + (s - v);
}

__device__ __forceinline__ float block_max_256(float v, float* red) {
#pragma unroll
    for (int o = 16; o > 0; o >>= 1) v = fmaxf(v, __shfl_xor_sync(0xffffffffu, v, o));
    if ((threadIdx.x & 31) == 0) red[threadIdx.x >> 5] = v;
    __syncthreads();
    return fmaxf(fmaxf(fmaxf(red[0], red[1]), fmaxf(red[2], red[3])),
                 fmaxf(fmaxf(red[4], red[5]), fmaxf(red[6], red[7])));
}

__device__ __forceinline__ float block_sum_256(float v, float* red) {
#pragma unroll
    for (int o = 16; o > 0; o >>= 1) v += __shfl_xor_sync(0xffffffffu, v, o);
    if ((threadIdx.x & 31) == 0) red[threadIdx.x >> 5] = v;
    __syncthreads();
    return ((red[0] + red[1]) + (red[2] + red[3])) + ((red[4] + red[5]) + (red[6] + red[7]));
}

// ---------------------------------------------------------------------------
// Row top-k softmax reduce. One block (256 thr) per (b, row).
//   m = row max, denom = full softmax denominator,
//   T = exact 32-bit key of the 128th largest score
//       (12-bit radix pass over 2048 elems -> candidate list -> 3 small passes),
//   out[d] = sum_sel exp(s-m)/denom * V[i][d]  (index-ordered, deterministic).
// ---------------------------------------------------------------------------
struct RSmem {
    float    scores[SEQ];     // 8 KB
    unsigned hist[4096];      // 16 KB; reused as candidate key list
    unsigned hist256[256];    // small per-pass histogram
    unsigned ws[8];
    float    red[8];
    int      sel_idx[KTOP];
    float    sel_w[KTOP];
    float    racc[256];
    int      boundary_bin;
    int      want_rem;
    int      cand_cnt;
    int      total_sel;
};

__global__ __launch_bounds__(256) void topk_reduce_kernel(const float* __restrict__ simbase,
                                                          const float* __restrict__ V,
                                                          const unsigned char* __restrict__ kmask,
                                                          const unsigned char* __restrict__ rmask,
                                                          float* __restrict__ out) {
    __shared__ RSmem sm;
    const int t = threadIdx.x;
    const int r = blockIdx.x;
    const int b = blockIdx.y;

    const float* srow = simbase + ((size_t)b * SEQ + r) * SEQ;
    const unsigned char* km = kmask + (size_t)b * SEQ;
    const int base = t * 8;

    // ---- stage masked scores (each thread owns 8 contiguous elems) + local max
    float vs[8];
    {
        float4 a0 = *(const float4*)(srow + base);
        float4 a1 = *(const float4*)(srow + base + 4);
        unsigned long long mk = *(const unsigned long long*)(km + base);
        vs[0] = a0.x; vs[1] = a0.y; vs[2] = a0.z; vs[3] = a0.w;
        vs[4] = a1.x; vs[5] = a1.y; vs[6] = a1.z; vs[7] = a1.w;
#pragma unroll
        for (int j = 0; j < 8; j++)
            if ((mk >> (8 * j)) & 0xffull) vs[j] = -FLT_MAX;
#pragma unroll
        for (int j = 0; j < 8; j++) sm.scores[base + j] = vs[j];
    }
    float lm = vs[0];
#pragma unroll
    for (int j = 1; j < 8; j++) lm = fmaxf(lm, vs[j]);
    const float m = block_max_256(lm, sm.red);

    // ---- zero 12-bit histogram
#pragma unroll
    for (int j = 0; j < 16; j++) sm.hist[t * 16 + j] = 0u;
    __syncthreads();

    // ---- denom + 12-bit histogram (fused)
    float ld = 0.f;
#pragma unroll
    for (int j = 0; j < 8; j++) {
        ld += __expf(vs[j] - m);
        atomicAdd(&sm.hist[f2key(vs[j]) >> 20], 1u);
    }
    const float denom = block_sum_256(ld, sm.red);  // its barrier also publishes hist

    // ---- scan 4096 bins from the top; locate boundary bin for rank 128
    {
        unsigned cnt[16], tot = 0;
#pragma unroll
        for (int j = 0; j < 16; j++) { cnt[j] = sm.hist[t * 16 + j]; tot += cnt[j]; }
        unsigned se = suffix_excl_256(tot, sm.ws);
        unsigned cum = se;
#pragma unroll
        for (int j = 15; j >= 0; j--) {
            unsigned ci = cum + cnt[j];
            if (cum < (unsigned)KTOP && ci >= (unsigned)KTOP) {
                sm.boundary_bin = t * 16 + j;
                sm.want_rem     = KTOP - (int)cum;
            }
            cum = ci;
        }
    }
    if (t == 0) sm.cand_cnt = 0;
    __syncthreads();

    const unsigned bb = (unsigned)sm.boundary_bin;
    int wrem = sm.want_rem;

    // ---- collect boundary-bin candidate keys (order-independent use)
#pragma unroll
    for (int j = 0; j < 8; j++) {
        unsigned k = f2key(vs[j]);
        if ((k >> 20) == bb) {
            int p = atomicAdd(&sm.cand_cnt, 1);
            sm.hist[p] = k;  // reuse hist storage as candidate list (cap 4096 >= 2048)
        }
    }
    __syncthreads();
    const int c = sm.cand_cnt;

    // ---- resolve remaining 20 bits of the threshold over the candidate list
    unsigned known = bb << 20;
    const int shifts[3] = {12, 4, 0};
    const int widths[3] = {8, 8, 4};
#pragma unroll
    for (int p = 0; p < 3; p++) {
        const int shift = shifts[p];
        const int bins  = 1 << widths[p];
        const int hi    = shift + widths[p];
        sm.hist256[t] = 0u;
        __syncthreads();
        for (int i = t; i < c; i += 256) {
            unsigned k = sm.hist[i];
            if ((k >> hi) == (known >> hi))
                atomicAdd(&sm.hist256[(k >> shift) & (bins - 1)], 1u);
        }
        __syncthreads();
        unsigned v  = (t < bins) ? sm.hist256[t] : 0u;
        unsigned se = suffix_excl_256(v, sm.ws);
        if (t < bins && (int)se < wrem && (int)(se + v) >= wrem) {
            sm.boundary_bin = t;
            sm.want_rem     = wrem - (int)se;
        }
        __syncthreads();
        known |= ((unsigned)sm.boundary_bin) << shift;
        wrem = sm.want_rem;
    }
    const unsigned T = known;  // exact key of the KTOP-th largest

    // ---- index-ordered compaction of keys >= T (deterministic)
    unsigned flags = 0, ls = 0;
#pragma unroll
    for (int j = 0; j < 8; j++)
        if (f2key(vs[j]) >= T) { flags |= (1u << j); ls++; }
    unsigned pe = prefix_excl_256(ls, sm.ws);
    if (t == 255) sm.total_sel = (int)(pe + ls);
    {
        int pos = (int)pe;
#pragma unroll
        for (int j = 0; j < 8; j++)
            if (flags & (1u << j)) {
                if (pos < KTOP) {
                    sm.sel_idx[pos] = base + j;
                    sm.sel_w[pos]   = __expf(vs[j] - m);
                }
                pos++;
            }
    }
    __syncthreads();
    const int n = min(sm.total_sel, KTOP);

    // ---- gather-accumulate: 4 partial slots x 64 dims
    const float* Vb = V + (size_t)b * SEQ * DIM;
    const int d    = t & 63;
    const int part = t >> 6;
    float acc = 0.f;
    for (int j = part; j < n; j += 4)
        acc += sm.sel_w[j] * __ldg(&Vb[(size_t)sm.sel_idx[j] * DIM + d]);
    sm.racc[t] = acc;
    __syncthreads();
    if (part == 0) {
        const bool rmk = rmask[(size_t)b * SEQ + r] != 0;
        float tot = sm.racc[d] + sm.racc[d + 64] + sm.racc[d + 128] + sm.racc[d + 192];
        out[((size_t)b * SEQ + r) * DIM + d] = rmk ? 0.f : tot * (1.f / denom);
    }
}

// ---------------------------------------------------------------------------
// Launch
// ---------------------------------------------------------------------------
extern "C" void kernel_launch(void* const* d_in, const int* in_sizes, int n_in,
                              void* d_out, int out_size) {
    const float*         v1  = (const float*)d_in[0];
    const unsigned char* v1m = (const unsigned char*)d_in[1];
    const float*         v2  = (const float*)d_in[2];
    const unsigned char* v2m = (const unsigned char*)d_in[3];
    float* out1 = (float*)d_out;
    float* out2 = out1 + (size_t)BATCH * SEQ * DIM;

    float* simp;  cudaGetSymbolAddress((void**)&simp,  g_sim);
    float* simtp; cudaGetSymbolAddress((void**)&simtp, g_simT);

    const int gemm_smem = 2 * 64 * 128 * (int)sizeof(float);  // 64 KB
    cudaFuncSetAttribute((const void*)gemm_kernel,
                         cudaFuncAttributeMaxDynamicSharedMemorySize, gemm_smem);

    dim3 gg(SEQ / 128, SEQ / 128, BATCH);
    gemm_kernel<<<gg, 256, gemm_smem>>>(v1, v2);

    dim3 gr(SEQ, BATCH);
    // direction 1: rows of sim attend over v2 (keys masked by v2_mask, rows by v1_mask)
    topk_reduce_kernel<<<gr, 256>>>(simp,  v2, v2m, v1m, out1);
    // direction 2: rows of simT attend over v1
    topk_reduce_kernel<<<gr, 256>>>(simtp, v1, v1m, v2m, out2);
}

// round 3
// speedup vs baseline: 1.6359x; 1.2274x over previous
#include <cuda_runtime.h>
#include <cuda_bf16.h>
#include <cfloat>
#include <cstdint>
#include <cstddef>

#define BATCH 16
#define SEQ   2048
#define DIM   64
#define KTOP  128

// 268 MB each: sim[b][q][k] and its transpose simT[b][k][q]
__device__ float g_sim [(size_t)BATCH * SEQ * SEQ];
__device__ float g_simT[(size_t)BATCH * SEQ * SEQ];

// Order-preserving float -> uint key (larger float => larger key)
__device__ __forceinline__ unsigned f2key(float f) {
    unsigned u = __float_as_uint(f);
    return u ^ (((unsigned)((int)u >> 31)) | 0x80000000u);
}

// ---------------------------------------------------------------------------
// GEMM: sim = v1 @ v2^T, simT = v2 @ v1^T (via smem-staged transpose).
// 128x128 tile per block, 256 threads, 8x8 per thread, K = 64 full depth.
// ---------------------------------------------------------------------------
__global__ __launch_bounds__(256, 2) void gemm_kernel(const float* __restrict__ v1,
                                                      const float* __restrict__ v2) {
    extern __shared__ float dsm[];
    float (*AsT)[128] = (float (*)[128])dsm;              // [d][q_local]
    float (*BsT)[128] = (float (*)[128])(dsm + 64 * 128); // [d][k_local]

    const int t  = threadIdx.x;
    const int b  = blockIdx.z;
    const int q0 = blockIdx.y * 128;
    const int k0 = blockIdx.x * 128;

    {
        const int r  = t & 127;
        const int ds = (t >> 7) * 32;
        const float* a  = v1 + ((size_t)b * SEQ + q0 + r) * DIM + ds;
        const float* bp = v2 + ((size_t)b * SEQ + k0 + r) * DIM + ds;
#pragma unroll
        for (int i = 0; i < 8; i++) {
            float4 va = *(const float4*)(a + 4 * i);
            AsT[ds + 4 * i + 0][r] = va.x;
            AsT[ds + 4 * i + 1][r] = va.y;
            AsT[ds + 4 * i + 2][r] = va.z;
            AsT[ds + 4 * i + 3][r] = va.w;
            float4 vb = *(const float4*)(bp + 4 * i);
            BsT[ds + 4 * i + 0][r] = vb.x;
            BsT[ds + 4 * i + 1][r] = vb.y;
            BsT[ds + 4 * i + 2][r] = vb.z;
            BsT[ds + 4 * i + 3][r] = vb.w;
        }
    }
    __syncthreads();

    const int tx = t & 15;
    const int ty = t >> 4;

    float acc[8][8];
#pragma unroll
    for (int i = 0; i < 8; i++)
#pragma unroll
        for (int j = 0; j < 8; j++) acc[i][j] = 0.f;

#pragma unroll 8
    for (int d = 0; d < 64; d++) {
        float ar[8], br[8];
        *(float4*)&ar[0] = *(const float4*)&AsT[d][ty * 8];
        *(float4*)&ar[4] = *(const float4*)&AsT[d][ty * 8 + 4];
        *(float4*)&br[0] = *(const float4*)&BsT[d][tx * 8];
        *(float4*)&br[4] = *(const float4*)&BsT[d][tx * 8 + 4];
#pragma unroll
        for (int i = 0; i < 8; i++)
#pragma unroll
            for (int j = 0; j < 8; j++) acc[i][j] = fmaf(ar[i], br[j], acc[i][j]);
    }

    // ---- coalesced sim store (row-major, natural layout)
    float* orow = g_sim + ((size_t)b * SEQ + q0 + ty * 8) * SEQ + k0 + tx * 8;
#pragma unroll
    for (int i = 0; i < 8; i++) {
        *(float4*)(orow + (size_t)i * SEQ)     = make_float4(acc[i][0], acc[i][1], acc[i][2], acc[i][3]);
        *(float4*)(orow + (size_t)i * SEQ + 4) = make_float4(acc[i][4], acc[i][5], acc[i][6], acc[i][7]);
    }

    // ---- simT store, staged through smem in 4 chunks of 32 k-rows x 128 q-cols
    float (*Ts)[129] = (float (*)[129])dsm;  // 32 x 129 floats = 16.5 KB (reuse)
#pragma unroll
    for (int kc = 0; kc < 4; kc++) {
        __syncthreads();
        if ((tx >> 2) == kc) {
            const int kl = (tx & 3) * 8;
            const int ql = ty * 8;
#pragma unroll
            for (int j = 0; j < 8; j++)
#pragma unroll
                for (int i = 0; i < 8; i++)
                    Ts[kl + j][ql + i] = acc[i][j];
        }
        __syncthreads();
        // 32 rows x 128 cols = 1024 float4s; coalesced 512B bursts per row segment
#pragma unroll
        for (int e = t; e < 1024; e += 256) {
            const int rr = e >> 5;
            const int cc = (e & 31) * 4;
            float4 o;
            o.x = Ts[rr][cc];
            o.y = Ts[rr][cc + 1];
            o.z = Ts[rr][cc + 2];
            o.w = Ts[rr][cc + 3];
            *(float4*)(g_simT + ((size_t)b * SEQ + k0 + kc * 32 + rr) * SEQ + q0 + cc) = o;
        }
    }
}

// ---------------------------------------------------------------------------
// Block scan helpers (256 threads)
// ---------------------------------------------------------------------------
__device__ __forceinline__ unsigned suffix_excl_256(unsigned v, unsigned* ws) {
    __syncthreads();  // protect ws reuse across calls
    const int lane = threadIdx.x & 31;
    unsigned s = v;
#pragma unroll
    for (int o = 1; o < 32; o <<= 1) {
        unsigned n = __shfl_down_sync(0xffffffffu, s, o);
        if (lane + o < 32) s += n;
    }
    if (lane == 0) ws[threadIdx.x >> 5] = s;
    __syncthreads();
    unsigned cross = 0;
    const int w = threadIdx.x >> 5;
#pragma unroll
    for (int i = 0; i < 8; i++)
        if (i > w) cross += ws[i];
    return cross + (s - v);
}

__device__ __forceinline__ unsigned prefix_excl_256(unsigned v, unsigned* ws) {
    __syncthreads();
    const int lane = threadIdx.x & 31;
    unsigned s = v;
#pragma unroll
    for (int o = 1; o < 32; o <<= 1) {
        unsigned n = __shfl_up_sync(0xffffffffu, s, o);
        if (lane - o >= 0) s += n;
    }
    if (lane == 31) ws[threadIdx.x >> 5] = s;
    __syncthreads();
    unsigned cross = 0;
    const int w = threadIdx.x >> 5;
#pragma unroll
    for (int i = 0; i < 8; i++)
        if (i < w) cross += ws[i];
    return cross + (s - v);
}

__device__ __forceinline__ float block_max_256(float v, float* red) {
#pragma unroll
    for (int o = 16; o > 0; o >>= 1) v = fmaxf(v, __shfl_xor_sync(0xffffffffu, v, o));
    if ((threadIdx.x & 31) == 0) red[threadIdx.x >> 5] = v;
    __syncthreads();
    return fmaxf(fmaxf(fmaxf(red[0], red[1]), fmaxf(red[2], red[3])),
                 fmaxf(fmaxf(red[4], red[5]), fmaxf(red[6], red[7])));
}

__device__ __forceinline__ float block_sum_256(float v, float* red) {
#pragma unroll
    for (int o = 16; o > 0; o >>= 1) v += __shfl_xor_sync(0xffffffffu, v, o);
    if ((threadIdx.x & 31) == 0) red[threadIdx.x >> 5] = v;
    __syncthreads();
    return ((red[0] + red[1]) + (red[2] + red[3])) + ((red[4] + red[5]) + (red[6] + red[7]));
}

// ---------------------------------------------------------------------------
// Row top-k softmax reduce. One block (256 thr) per (b, row).
// ---------------------------------------------------------------------------
struct RSmem {
    unsigned hist[2048];      // 8 KB; 11-bit histogram, reused as candidate list
    unsigned hist256[256];
    unsigned ws[8];
    float    red[8];
    int      sel_idx[KTOP];
    float    sel_w[KTOP];
    float    wacc[8][64];
    int      boundary_bin;
    int      want_rem;
    int      cand_cnt;
    int      ng;
    int      neq;
};

__global__ __launch_bounds__(256) void topk_reduce_kernel(const float* __restrict__ simbase,
                                                          const float* __restrict__ V,
                                                          const unsigned char* __restrict__ kmask,
                                                          const unsigned char* __restrict__ rmask,
                                                          float* __restrict__ out) {
    __shared__ RSmem sm;
    const int t = threadIdx.x;
    const int r = blockIdx.x;
    const int b = blockIdx.y;

    const float* srow = simbase + ((size_t)b * SEQ + r) * SEQ;
    const unsigned char* km = kmask + (size_t)b * SEQ;
    const int base = t * 8;

    // ---- load masked scores (8 contiguous per thread), streaming hint
    float vs[8];
    {
        float4 a0 = __ldcs((const float4*)(srow + base));
        float4 a1 = __ldcs((const float4*)(srow + base + 4));
        unsigned long long mk = *(const unsigned long long*)(km + base);
        vs[0] = a0.x; vs[1] = a0.y; vs[2] = a0.z; vs[3] = a0.w;
        vs[4] = a1.x; vs[5] = a1.y; vs[6] = a1.z; vs[7] = a1.w;
#pragma unroll
        for (int j = 0; j < 8; j++)
            if ((mk >> (8 * j)) & 0xffull) vs[j] = -FLT_MAX;
    }
    float lm = vs[0];
#pragma unroll
    for (int j = 1; j < 8; j++) lm = fmaxf(lm, vs[j]);
    const float m = block_max_256(lm, sm.red);

    // ---- zero 11-bit histogram
#pragma unroll
    for (int j = 0; j < 8; j++) sm.hist[t * 8 + j] = 0u;
    __syncthreads();

    // ---- denom + histogram (fused)
    float ld = 0.f;
#pragma unroll
    for (int j = 0; j < 8; j++) {
        ld += __expf(vs[j] - m);
        atomicAdd(&sm.hist[f2key(vs[j]) >> 21], 1u);
    }
    const float denom = block_sum_256(ld, sm.red);  // barrier also publishes hist

    // ---- scan 2048 bins from the top; locate boundary bin for rank KTOP
    {
        unsigned cnt[8], tot = 0;
#pragma unroll
        for (int j = 0; j < 8; j++) { cnt[j] = sm.hist[t * 8 + j]; tot += cnt[j]; }
        unsigned se = suffix_excl_256(tot, sm.ws);
        unsigned cum = se;
#pragma unroll
        for (int j = 7; j >= 0; j--) {
            unsigned ci = cum + cnt[j];
            if (cum < (unsigned)KTOP && ci >= (unsigned)KTOP) {
                sm.boundary_bin = t * 8 + j;
                sm.want_rem     = KTOP - (int)cum;
            }
            cum = ci;
        }
    }
    if (t == 0) sm.cand_cnt = 0;
    __syncthreads();

    const unsigned bb = (unsigned)sm.boundary_bin;
    int wrem = sm.want_rem;

    // ---- collect boundary-bin candidate keys (reuse hist as list; cap 2048)
#pragma unroll
    for (int j = 0; j < 8; j++) {
        unsigned k = f2key(vs[j]);
        if ((k >> 21) == bb) {
            int p = atomicAdd(&sm.cand_cnt, 1);
            sm.hist[p] = k;
        }
    }
    __syncthreads();
    const int c = sm.cand_cnt;

    // ---- resolve remaining 21 bits over the candidate list: widths 8,8,5
    unsigned known = bb << 21;
    const int shifts[3] = {13, 5, 0};
    const int widths[3] = {8, 8, 5};
#pragma unroll
    for (int p = 0; p < 3; p++) {
        const int shift = shifts[p];
        const int bins  = 1 << widths[p];
        const int hi    = shift + widths[p];
        sm.hist256[t] = 0u;
        __syncthreads();
        for (int i = t; i < c; i += 256) {
            unsigned k = sm.hist[i];
            if ((k >> hi) == (known >> hi))
                atomicAdd(&sm.hist256[(k >> shift) & (bins - 1)], 1u);
        }
        __syncthreads();
        unsigned v  = (t < bins) ? sm.hist256[t] : 0u;
        unsigned se = suffix_excl_256(v, sm.ws);
        if (t < bins && (int)se < wrem && (int)(se + v) >= wrem) {
            sm.boundary_bin = t;
            sm.want_rem     = wrem - (int)se;
        }
        __syncthreads();
        known |= ((unsigned)sm.boundary_bin) << shift;
        wrem = sm.want_rem;
    }
    const unsigned T = known;  // exact key of the KTOP-th largest

    // ---- reference-exact selection: all keys > T, then earliest keys == T
    unsigned fgt = 0, feq = 0;
    unsigned lgt = 0, leq = 0;
#pragma unroll
    for (int j = 0; j < 8; j++) {
        unsigned k = f2key(vs[j]);
        if (k > T)       { fgt |= (1u << j); lgt++; }
        else if (k == T) { feq |= (1u << j); leq++; }
    }
    unsigned pg = prefix_excl_256(lgt, sm.ws);
    if (t == 255) sm.ng = (int)(pg + lgt);
    unsigned pe = prefix_excl_256(leq, sm.ws);  // leading barrier publishes sm.ng
    if (t == 255) sm.neq = (int)(pe + leq);
    const int ng = sm.ng;
    {
        int pos = (int)pg;
#pragma unroll
        for (int j = 0; j < 8; j++)
            if (fgt & (1u << j)) {
                sm.sel_idx[pos] = base + j;
                sm.sel_w[pos]   = __expf(vs[j] - m);
                pos++;
            }
        pos = ng + (int)pe;
#pragma unroll
        for (int j = 0; j < 8; j++)
            if (feq & (1u << j)) {
                if (pos < KTOP) {
                    sm.sel_idx[pos] = base + j;
                    sm.sel_w[pos]   = __expf(vs[j] - m);
                }
                pos++;
            }
    }
    __syncthreads();
    const int n = min(KTOP, ng + sm.neq);

    // ---- gather: half-warp per selected row, 8 independent float4 loads in flight
    const float* Vb = V + (size_t)b * SEQ * DIM;
    const int w    = t >> 5;
    const int lane = t & 31;
    const int half = lane >> 4;
    const int li   = lane & 15;
    float4 acc = make_float4(0.f, 0.f, 0.f, 0.f);
#pragma unroll
    for (int it = 0; it < 8; it++) {
        const int j = it * 16 + w * 2 + half;
        if (j < n) {
            const int   idx = sm.sel_idx[j];
            const float wgt = sm.sel_w[j];
            const float4 val = __ldg((const float4*)(Vb + (size_t)idx * DIM + li * 4));
            acc.x = fmaf(wgt, val.x, acc.x);
            acc.y = fmaf(wgt, val.y, acc.y);
            acc.z = fmaf(wgt, val.z, acc.z);
            acc.w = fmaf(wgt, val.w, acc.w);
        }
    }
    acc.x += __shfl_xor_sync(0xffffffffu, acc.x, 16);
    acc.y += __shfl_xor_sync(0xffffffffu, acc.y, 16);
    acc.z += __shfl_xor_sync(0xffffffffu, acc.z, 16);
    acc.w += __shfl_xor_sync(0xffffffffu, acc.w, 16);
    if (half == 0) *(float4*)&sm.wacc[w][li * 4] = acc;
    __syncthreads();
    if (t < 64) {
        float s = 0.f;
#pragma unroll
        for (int ww = 0; ww < 8; ww++) s += sm.wacc[ww][t];
        const bool rmk = rmask[(size_t)b * SEQ + r] != 0;
        out[((size_t)b * SEQ + r) * DIM + t] = rmk ? 0.f : s * (1.f / denom);
    }
}

// ---------------------------------------------------------------------------
// Launch
// ---------------------------------------------------------------------------
extern "C" void kernel_launch(void* const* d_in, const int* in_sizes, int n_in,
                              void* d_out, int out_size) {
    const float*         v1  = (const float*)d_in[0];
    const unsigned char* v1m = (const unsigned char*)d_in[1];
    const float*         v2  = (const float*)d_in[2];
    const unsigned char* v2m = (const unsigned char*)d_in[3];
    float* out1 = (float*)d_out;
    float* out2 = out1 + (size_t)BATCH * SEQ * DIM;

    float* simp;  cudaGetSymbolAddress((void**)&simp,  g_sim);
    float* simtp; cudaGetSymbolAddress((void**)&simtp, g_simT);

    const int gemm_smem = 2 * 64 * 128 * (int)sizeof(float);  // 64 KB
    cudaFuncSetAttribute((const void*)gemm_kernel,
                         cudaFuncAttributeMaxDynamicSharedMemorySize, gemm_smem);

    dim3 gg(SEQ / 128, SEQ / 128, BATCH);
    gemm_kernel<<<gg, 256, gemm_smem>>>(v1, v2);

    dim3 gr(SEQ, BATCH);
    topk_reduce_kernel<<<gr, 256>>>(simp,  v2, v2m, v1m, out1);
    topk_reduce_kernel<<<gr, 256>>>(simtp, v1, v1m, v2m, out2);
}